// round 1
// baseline (speedup 1.0000x reference)
#include <cuda_runtime.h>
#include <cuda_bf16.h>

#define LOOK_SHORT 21
#define LOOK_LONG  63
#define NFEAT      16
#define ROW_STRIDE (LOOK_LONG * NFEAT)   // 1008 floats per batch row
#define NOUT       21
#define WARPS_PER_BLOCK 8

__device__ __forceinline__ float warp_sum(float v) {
#pragma unroll
    for (int o = 16; o > 0; o >>= 1) v += __shfl_xor_sync(0xffffffffu, v, o);
    return v;
}
__device__ __forceinline__ float warp_max(float v) {
#pragma unroll
    for (int o = 16; o > 0; o >>= 1) v = fmaxf(v, __shfl_xor_sync(0xffffffffu, v, o));
    return v;
}
__device__ __forceinline__ float warp_min(float v) {
#pragma unroll
    for (int o = 16; o > 0; o >>= 1) v = fminf(v, __shfl_xor_sync(0xffffffffu, v, o));
    return v;
}

__global__ __launch_bounds__(WARPS_PER_BLOCK * 32)
void regime_feature_kernel(const float* __restrict__ x,
                           float* __restrict__ out,
                           int B) {
    const int warp_in_blk = threadIdx.x >> 5;
    const int lane        = threadIdx.x & 31;
    const int row         = blockIdx.x * WARPS_PER_BLOCK + warp_in_blk;
    if (row >= B) return;

    __shared__ float s_r[WARPS_PER_BLOCK][LOOK_LONG + 1];
    float* r = s_r[warp_in_blk];

    const float* __restrict__ xr = x + (size_t)row * ROW_STRIDE;

    // ---- load r (column 0) : t = lane and t = lane+32 (lane<31) ----
    float r0 = xr[lane * NFEAT + 0];
    r[lane] = r0;
    float r1 = 0.0f;
    const bool has2 = (lane < 31);           // t=32..62
    if (has2) {
        r1 = xr[(lane + 32) * NFEAT + 0];
        r[lane + 32] = r1;
    }
    // volf (column 10) for last 21 timesteps: t = 42+lane, lane<21
    float vf = (lane < LOOK_SHORT) ? xr[(42 + lane) * NFEAT + 10] : 0.0f;

    __syncwarp();

    // ---- pass-1 reductions ----
    float v1 = r0, v2 = has2 ? r1 : 0.0f;
    float sum    = warp_sum(v1 + v2);
    float sumsq  = warp_sum(v1 * v1 + v2 * v2);
    float sumabs = warp_sum(fabsf(v1) + fabsf(v2));
    // short window: t in [42,62] -> second value of lanes 10..30
    const bool in_short = has2 && (lane >= 10);
    float sv  = in_short ? r1 : 0.0f;
    float ssum   = warp_sum(sv);
    float ssumsq = warp_sum(sv * sv);
    // lag-1 cross product: t = lane (<=31<=61) and t = lane+32 (lane<=29)
    float ab = r0 * r[lane + 1];
    if (lane <= 29) ab += r1 * r[lane + 33];
    float sum_ab = warp_sum(ab);
    float vf_sum = warp_sum(vf);
    float rmax = warp_max(fmaxf(v1, has2 ? r1 : v1));
    float rmin = warp_min(fminf(v1, has2 ? r1 : v1));

    // ---- derived stats ----
    const float n  = 63.0f;
    float mean     = sum / n;
    float var_long = fmaxf(0.0f, (sumsq - sum * sum / n)) / 62.0f;
    float vol_long = sqrtf(var_long);
    float var_s    = fmaxf(0.0f, (ssumsq - ssum * ssum / 21.0f)) / 20.0f;
    float vol_short = sqrtf(var_s);
    float vol_ratio = vol_short / (vol_long + 1e-8f);
    float high_vol = (vol_short > 0.03f) ? 1.0f : 0.0f;
    float med_vol  = ((vol_short >= 0.01f) && (vol_short <= 0.03f)) ? 1.0f : 0.0f;
    float low_vol  = (vol_short < 0.01f) ? 1.0f : 0.0f;

    // corr(a=r[0..61], b=r[1..62]) using derived sums
    float rfirst = r[0], rlast = r[62];
    float sa  = sum - rlast;
    float sb  = sum - rfirst;
    float saa = sumsq - rlast * rlast;
    float sbb = sumsq - rfirst * rfirst;
    float cnum = sum_ab - sa * sb / 62.0f;
    float cden = sqrtf((saa - sa * sa / 62.0f) * (sbb - sb * sb / 62.0f));
    float corr = cnum / cden;
    float trend_strength = (corr != corr) ? 0.5f : fabsf(corr);

    // ---- pass-2: skewness (two-pass, centered cubes) ----
    float d1 = r0 - mean;
    float d2 = has2 ? (r1 - mean) : 0.0f;
    float sum_c3 = warp_sum(d1 * d1 * d1 + d2 * d2 * d2);
    float skewness = 0.0f;
    if (vol_long >= 1e-8f) {
        float inv_s3 = 1.0f / (vol_long * vol_long * vol_long);
        skewness = (sum_c3 / n) * inv_s3;
    }

    float momentum_short = rlast / (r[42] + 1e-8f) - 1.0f;
    float return_range   = rmax - rmin;
    float vol_feature_mean = vf_sum / 21.0f;

    // ---- sliding-window stds: js = 62,57,...,22 (9 windows of 22 elems, ddof=1)
    float vs_l = 0.0f;
    if (lane < 9) {
        int j = 62 - 5 * lane;
        float ws = 0.0f, wss = 0.0f;
#pragma unroll
        for (int k = 0; k < 22; ++k) {
            float v = r[j - 21 + k];
            ws += v;
            wss += v * v;
        }
        vs_l = sqrtf(fmaxf(0.0f, (wss - ws * ws / 22.0f)) / 21.0f);
    }
    float vs_sum  = warp_sum(vs_l);
    float vs_sum2 = warp_sum(vs_l * vs_l);
    float m_vs = vs_sum / 9.0f;
    float vol_persistence = sqrtf(fmaxf(0.0f, vs_sum2 / 9.0f - m_vs * m_vs));
    float vs_first = __shfl_sync(0xffffffffu, vs_l, 0);
    float vs_last  = __shfl_sync(0xffffffffu, vs_l, 8);
    float vol_trend = vs_first - vs_last;

    // ---- write 21 features, coalesced across lanes 0..20 ----
    float fv = 0.0f;
    switch (lane) {
        case 0:  fv = high_vol; break;
        case 1:  fv = med_vol; break;
        case 2:  fv = low_vol; break;
        case 3:  fv = trend_strength; break;
        case 4:  fv = vol_ratio; break;
        case 5:  fv = mean; break;
        case 6:  fv = sumabs / n; break;
        case 7:  fv = return_range; break;
        case 8:  fv = skewness; break;
        case 9:  fv = momentum_short; break;
        case 10: fv = xr[62 * NFEAT + 1];  break;   // rsi_current (L1/L2-hot sector)
        case 11: fv = vol_feature_mean; break;
        case 12: fv = xr[62 * NFEAT + 15]; break;   // momentum_feature_current
        case 13: fv = 0.0f; break;                  // relative_return
        case 14: fv = 1.0f; break;                  // relative_vol
        case 15: fv = 1.0f; break;                  // beta
        case 16: fv = 0.0f; break;                  // relative_strength
        case 17: fv = 0.02f; break;                 // market_vol_level
        case 18: fv = vol_persistence; break;
        case 19: fv = vol_trend; break;
        case 20: fv = 0.0f; break;                  // regime_shift
        default: break;
    }
    if (lane < NOUT) out[(size_t)row * NOUT + lane] = fv;
}

extern "C" void kernel_launch(void* const* d_in, const int* in_sizes, int n_in,
                              void* d_out, int out_size) {
    const float* x = (const float*)d_in[0];
    float* out = (float*)d_out;
    int B = in_sizes[0] / ROW_STRIDE;
    int blocks = (B + WARPS_PER_BLOCK - 1) / WARPS_PER_BLOCK;
    regime_feature_kernel<<<blocks, WARPS_PER_BLOCK * 32>>>(x, out, B);
}